// round 11
// baseline (speedup 1.0000x reference)
#include <cuda_runtime.h>
#include <cstddef>

#define BB 256
#define TT 2048
#define NXX 64
#define NUU 32
#define NYY 16
#define HH 128

typedef unsigned long long u64;

// BAR_A: dx-warps + g-warps only (192 threads, tid 160..351). B: full CTA (352).
#define BAR_A() asm volatile("bar.sync 1, 192;" ::: "memory")

// Packed fp32x2 helpers (per-lane IEEE fma.rn, identical to scalar fma.rn.f32).
__device__ __forceinline__ u64 pk2(float lo, float hi) {
    u64 r; asm("mov.b64 %0, {%1, %2};" : "=l"(r) : "f"(lo), "f"(hi)); return r;
}
__device__ __forceinline__ void upk2(u64 v, float& lo, float& hi) {
    asm("mov.b64 {%0, %1}, %2;" : "=f"(lo), "=f"(hi) : "l"(v));
}
__device__ __forceinline__ u64 fma2(u64 a, u64 b, u64 c) {
    u64 d; asm("fma.rn.f32x2 %0, %1, %2, %3;" : "=l"(d) : "l"(a), "l"(b), "l"(c)); return d;
}

// IEEE round-to-nearest divide, immune to fast-math substitution.
__device__ __forceinline__ float fdiv_rn(float a, float b) {
    float r; asm("div.rn.f32 %0, %1, %2;" : "=f"(r) : "f"(a), "f"(b)); return r;
}

// Exact replication of XLA EmitFastTanh (FMA-capable target). DO NOT TOUCH.
__device__ __forceinline__ float xla_tanh(float x) {
    const float kClamp = 7.99881172180175781f;
    float xc = fmaxf(-kClamp, fminf(x, kClamp));
    float x2 = __fmul_rn(xc, xc);
    float p = fmaf(x2, -2.76076847742355e-16f, 2.00018790482477e-13f);
    p = fmaf(x2, p, -8.60467152213735e-11f);
    p = fmaf(x2, p,  5.12229709037114e-08f);
    p = fmaf(x2, p,  1.48572235717979e-05f);
    p = fmaf(x2, p,  6.37261928875436e-04f);
    p = fmaf(x2, p,  4.89352455891786e-03f);
    float num = __fmul_rn(xc, p);
    float q = fmaf(x2, 1.19825839466702e-06f, 1.18534705686654e-04f);
    q = fmaf(x2, q, 2.26843463243900e-03f);
    q = fmaf(x2, q, 4.89352518554385e-03f);
    float r = fdiv_rn(num, q);
    return (fabsf(x) < 0.0004f) ? x : r;
}

// 128 CTAs x 352 threads; 2 batch elements per CTA, packed lane-wise (f32x2).
// Role order chosen so the B300 hi-wid-first arbiter prioritizes critical warps:
//   tid   0.. 31 : y-warp (wid 0, lowest priority — fully slack, lagged).
//   tid  32..159 : h-warps (wid 1-4 — whole-step slack).
//   tid 160..223 : dx-warps (wid 5-6 — phase-2 critical chain).
//   tid 224..351 : g-warps (wid 7-10, highest — phase-1 critical chain).
// Per-lane accumulation orders identical to R6-R10 passing kernels (bit-exact).

__global__ __launch_bounds__(352, 1)
void ssm_kernel(const float* __restrict__ x0,
                const float* __restrict__ u,
                const float* __restrict__ Wg1, const float* __restrict__ bg1,
                const float* __restrict__ Wg2, const float* __restrict__ bg2,
                const float* __restrict__ Wh1, const float* __restrict__ bh1,
                const float* __restrict__ Wh2, const float* __restrict__ bh2,
                float* __restrict__ out_x, float* __restrict__ out_y)
{
    __shared__ __align__(16) float2 sxu2[2][96];   // [parity][k] = (e0,e1); 0..63 x, 64..95 u
    __shared__ __align__(16) float2 g1s2[HH];      // tanh(g layer-1) pairs
    __shared__ __align__(16) float2 h1p2[2][HH];   // tanh(h layer-1) pairs, double buffer

    const int tid = threadIdx.x;
    const int b0  = blockIdx.x * 2;

    // ---- init: x0, u0 into parity-0 buffer as pairs ----
    if (tid < 64) {
        sxu2[0][tid] = make_float2(x0[(size_t)(b0 + 0) * NXX + tid],
                                   x0[(size_t)(b0 + 1) * NXX + tid]);
    } else if (tid < 96) {
        int k = tid - 64;
        sxu2[0][64 + k] = make_float2(u[(size_t)(b0 + 0) * TT * NUU + k],
                                      u[(size_t)(b0 + 1) * TT * NUU + k]);
    }

    if (tid >= 224) {
        // ===================== g-warps (highest priority) =====================
        const int h = tid - 224;
        float wg1r[96];
        #pragma unroll
        for (int k = 0; k < 96; k++) wg1r[k] = Wg1[k * HH + h];
        const float bg1r = bg1[h];

        __syncthreads();  // init visible

        #pragma unroll 1
        for (int t = 0; t < TT; t++) {
            const int p = t & 1;
            const ulonglong2* x2 = (const ulonglong2*)&sxu2[p][0];

            u64 zg = pk2(0.f, 0.f);
            #pragma unroll
            for (int k2 = 0; k2 < 48; k2++) {       // 2 k per iter, k ascending
                const ulonglong2 v = x2[k2];
                zg = fma2(v.x, pk2(wg1r[2*k2+0], wg1r[2*k2+0]), zg);
                zg = fma2(v.y, pk2(wg1r[2*k2+1], wg1r[2*k2+1]), zg);
            }
            float zg0, zg1; upk2(zg, zg0, zg1);
            g1s2[h] = make_float2(xla_tanh(__fadd_rn(zg0, bg1r)),
                                  xla_tanh(__fadd_rn(zg1, bg1r)));
            BAR_A();          // g1 published -> dx chain starts
            __syncthreads();  // B
        }
    } else if (tid >= 160) {
        // ===================== dx-warps (one column j, both elements packed) =====
        const int q = tid - 160;        // 0..63
        const int j = q;

        float wg2r[128];
        #pragma unroll
        for (int i = 0; i < 128; i++) wg2r[i] = Wg2[i * NXX + j];
        const float bg2r = bg2[j];

        const size_t u_base0 = (size_t)(b0 + 0) * TT * NUU + q;  // q<32 duty
        const size_t u_base1 = (size_t)(b0 + 1) * TT * NUU + q;

        float xr0 = x0[(size_t)(b0 + 0) * NXX + j];
        float xr1 = x0[(size_t)(b0 + 1) * NXX + j];
        float* oxp0 = out_x + (size_t)(b0 + 0) * TT * NXX + j;
        float* oxp1 = out_x + (size_t)(b0 + 1) * TT * NXX + j;

        __syncthreads();  // init visible

        const ulonglong2* g2 = (const ulonglong2*)&g1s2[0];

        #pragma unroll 1
        for (int t = 0; t < TT; t++) {
            const int pn = (t + 1) & 1;

            // ---- phase 1: launch u(t+1) loads first, then record x_t ----
            float un0 = 0.f, un1 = 0.f;
            if (q < 32) {
                int tn = (t + 1 < TT) ? (t + 1) : (TT - 1);
                un0 = u[u_base0 + (size_t)tn * NUU];
                un1 = u[u_base1 + (size_t)tn * NUU];
            }
            *oxp0 = xr0;  oxp0 += NXX;
            *oxp1 = xr1;  oxp1 += NXX;
            BAR_A();  // g1 ready

            // ---- phase 2: packed sequential 128-dot (ascending i) ----
            u64 dxa = pk2(0.f, 0.f);
            #pragma unroll
            for (int i2 = 0; i2 < 64; i2++) {
                const ulonglong2 v = g2[i2];
                dxa = fma2(v.x, pk2(wg2r[2*i2+0], wg2r[2*i2+0]), dxa);
                dxa = fma2(v.y, pk2(wg2r[2*i2+1], wg2r[2*i2+1]), dxa);
            }
            float dxa0, dxa1; upk2(dxa, dxa0, dxa1);
            // pinned HLO order: x_{t+1} = x + (dot + bg2)
            xr0 = __fadd_rn(xr0, __fadd_rn(dxa0, bg2r));
            xr1 = __fadd_rn(xr1, __fadd_rn(dxa1, bg2r));
            sxu2[pn][j] = make_float2(xr0, xr1);
            if (q < 32) sxu2[pn][64 + q] = make_float2(un0, un1);
            __syncthreads();  // B
        }
    } else if (tid >= 32) {
        // ===================== h-warps (whole-step slack, B only) =================
        const int h = tid - 32;         // 0..127
        float wh1r[64];
        #pragma unroll
        for (int k = 0; k < 64; k++) wh1r[k] = Wh1[k * HH + h];
        const float bh1r = bh1[h];

        __syncthreads();  // init visible

        #pragma unroll 1
        for (int t = 0; t < TT; t++) {
            const int p = t & 1;
            const ulonglong2* x2 = (const ulonglong2*)&sxu2[p][0];

            u64 zh = pk2(0.f, 0.f);
            #pragma unroll
            for (int k2 = 0; k2 < 32; k2++) {
                const ulonglong2 v = x2[k2];
                zh = fma2(v.x, pk2(wh1r[2*k2+0], wh1r[2*k2+0]), zh);
                zh = fma2(v.y, pk2(wh1r[2*k2+1], wh1r[2*k2+1]), zh);
            }
            float zh0, zh1; upk2(zh, zh0, zh1);
            h1p2[p][h] = make_float2(xla_tanh(__fadd_rn(zh0, bh1r)),
                                     xla_tanh(__fadd_rn(zh1, bh1r)));
            __syncthreads();  // B: h1 committed with state
        }
    } else {
        // ===================== y-warp (wid 0, lagged, off the gate) ===============
        const int oo = tid;             // 0..31; active if oo<16

        float wh2r[128];
        const int oc = (oo < 16) ? oo : 0;
        #pragma unroll
        for (int i = 0; i < 128; i++) wh2r[i] = Wh2[i * NYY + oc];
        const float bh2r = bh2[oc];

        float* oyp0 = out_y + (size_t)(b0 + 0) * TT * NYY + oc;
        float* oyp1 = out_y + (size_t)(b0 + 1) * TT * NYY + oc;

        __syncthreads();  // init visible

        #pragma unroll 1
        for (int t = 0; t < TT; t++) {
            __syncthreads();  // B(t): h1p[t&1] ready
            const int pp = t & 1;
            const ulonglong2* h2 = (const ulonglong2*)&h1p2[pp][0];
            u64 ya = pk2(0.f, 0.f);
            #pragma unroll
            for (int i2 = 0; i2 < 64; i2++) {
                const ulonglong2 v = h2[i2];
                ya = fma2(v.x, pk2(wh2r[2*i2+0], wh2r[2*i2+0]), ya);
                ya = fma2(v.y, pk2(wh2r[2*i2+1], wh2r[2*i2+1]), ya);
            }
            float ya0, ya1; upk2(ya, ya0, ya1);
            if (oo < 16) {
                *oyp0 = __fadd_rn(ya0, bh2r);  oyp0 += NYY;
                *oyp1 = __fadd_rn(ya1, bh2r);  oyp1 += NYY;
            }
        }
    }
}

extern "C" void kernel_launch(void* const* d_in, const int* in_sizes, int n_in,
                              void* d_out, int out_size)
{
    const float* x0  = (const float*)d_in[0];
    const float* u   = (const float*)d_in[1];
    const float* Wg1 = (const float*)d_in[2];
    const float* bg1 = (const float*)d_in[3];
    const float* Wg2 = (const float*)d_in[4];
    const float* bg2 = (const float*)d_in[5];
    const float* Wh1 = (const float*)d_in[6];
    const float* bh1 = (const float*)d_in[7];
    const float* Wh2 = (const float*)d_in[8];
    const float* bh2 = (const float*)d_in[9];

    float* out_x = (float*)d_out;
    float* out_y = out_x + (size_t)BB * TT * NXX;

    ssm_kernel<<<BB / 2, 352>>>(x0, u, Wg1, bg1, Wg2, bg2,
                                Wh1, bh1, Wh2, bh2, out_x, out_y);
}

// round 12
// speedup vs baseline: 1.0376x; 1.0376x over previous
#include <cuda_runtime.h>
#include <cstddef>

#define BB 256
#define TT 2048
#define NXX 64
#define NUU 32
#define NYY 16
#define HH 128

typedef unsigned long long u64;

// BAR_A: h-warps + dx-warps + g-warps (320 threads, tid 32..351). B: full CTA (352).
#define BAR_A() asm volatile("bar.sync 1, 320;" ::: "memory")

// Packed fp32x2 helpers (per-lane IEEE fma.rn, identical to scalar fma.rn.f32).
__device__ __forceinline__ u64 pk2(float lo, float hi) {
    u64 r; asm("mov.b64 %0, {%1, %2};" : "=l"(r) : "f"(lo), "f"(hi)); return r;
}
__device__ __forceinline__ void upk2(u64 v, float& lo, float& hi) {
    asm("mov.b64 {%0, %1}, %2;" : "=f"(lo), "=f"(hi) : "l"(v));
}
__device__ __forceinline__ u64 fma2(u64 a, u64 b, u64 c) {
    u64 d; asm("fma.rn.f32x2 %0, %1, %2, %3;" : "=l"(d) : "l"(a), "l"(b), "l"(c)); return d;
}

// IEEE round-to-nearest divide, immune to fast-math substitution.
__device__ __forceinline__ float fdiv_rn(float a, float b) {
    float r; asm("div.rn.f32 %0, %1, %2;" : "=f"(r) : "f"(a), "f"(b)); return r;
}

// Exact replication of XLA EmitFastTanh (FMA-capable target). DO NOT TOUCH.
__device__ __forceinline__ float xla_tanh(float x) {
    const float kClamp = 7.99881172180175781f;
    float xc = fmaxf(-kClamp, fminf(x, kClamp));
    float x2 = __fmul_rn(xc, xc);
    float p = fmaf(x2, -2.76076847742355e-16f, 2.00018790482477e-13f);
    p = fmaf(x2, p, -8.60467152213735e-11f);
    p = fmaf(x2, p,  5.12229709037114e-08f);
    p = fmaf(x2, p,  1.48572235717979e-05f);
    p = fmaf(x2, p,  6.37261928875436e-04f);
    p = fmaf(x2, p,  4.89352455891786e-03f);
    float num = __fmul_rn(xc, p);
    float q = fmaf(x2, 1.19825839466702e-06f, 1.18534705686654e-04f);
    q = fmaf(x2, q, 2.26843463243900e-03f);
    q = fmaf(x2, q, 4.89352518554385e-03f);
    float r = fdiv_rn(num, q);
    return (fabsf(x) < 0.0004f) ? x : r;
}

// 128 CTAs x 352 threads; 2 batch elements per CTA, packed lane-wise (f32x2).
// Phase-balanced schedule:
//   phase 1 (B -> A): g-warps only (zg chains) + dx's STG/LDG + y's lagged dot.
//   phase 2 (A -> B): dx chain + h-warps (zh chains) — crossbar/issue spread out.
//   tid   0.. 31 : y-warp (joins B only; computes y(t-1) during phase 1 of t).
//   tid  32..159 : h-warps (wait A, work in phase 2, commit h1p before B).
//   tid 160..223 : dx-warps (phase-2 critical chain).
//   tid 224..351 : g-warps (phase-1 critical chain).
// Per-lane accumulation orders identical to R6-R11 passing kernels (bit-exact).

__global__ __launch_bounds__(352, 1)
void ssm_kernel(const float* __restrict__ x0,
                const float* __restrict__ u,
                const float* __restrict__ Wg1, const float* __restrict__ bg1,
                const float* __restrict__ Wg2, const float* __restrict__ bg2,
                const float* __restrict__ Wh1, const float* __restrict__ bh1,
                const float* __restrict__ Wh2, const float* __restrict__ bh2,
                float* __restrict__ out_x, float* __restrict__ out_y)
{
    __shared__ __align__(16) float2 sxu2[2][96];   // [parity][k] = (e0,e1); 0..63 x, 64..95 u
    __shared__ __align__(16) float2 g1s2[HH];      // tanh(g layer-1) pairs
    __shared__ __align__(16) float2 h1p2[2][HH];   // tanh(h layer-1) pairs, double buffer

    const int tid = threadIdx.x;
    const int b0  = blockIdx.x * 2;

    // ---- init: x0, u0 into parity-0 buffer as pairs ----
    if (tid < 64) {
        sxu2[0][tid] = make_float2(x0[(size_t)(b0 + 0) * NXX + tid],
                                   x0[(size_t)(b0 + 1) * NXX + tid]);
    } else if (tid < 96) {
        int k = tid - 64;
        sxu2[0][64 + k] = make_float2(u[(size_t)(b0 + 0) * TT * NUU + k],
                                      u[(size_t)(b0 + 1) * TT * NUU + k]);
    }

    if (tid >= 224) {
        // ===================== g-warps (phase-1 critical) =====================
        const int h = tid - 224;
        float wg1r[96];
        #pragma unroll
        for (int k = 0; k < 96; k++) wg1r[k] = Wg1[k * HH + h];
        const float bg1r = bg1[h];

        __syncthreads();  // init visible

        #pragma unroll 1
        for (int t = 0; t < TT; t++) {
            const int p = t & 1;
            const ulonglong2* x2 = (const ulonglong2*)&sxu2[p][0];

            u64 zg = pk2(0.f, 0.f);
            #pragma unroll
            for (int k2 = 0; k2 < 48; k2++) {       // 2 k per iter, k ascending
                const ulonglong2 v = x2[k2];
                zg = fma2(v.x, pk2(wg1r[2*k2+0], wg1r[2*k2+0]), zg);
                zg = fma2(v.y, pk2(wg1r[2*k2+1], wg1r[2*k2+1]), zg);
            }
            float zg0, zg1; upk2(zg, zg0, zg1);
            g1s2[h] = make_float2(xla_tanh(__fadd_rn(zg0, bg1r)),
                                  xla_tanh(__fadd_rn(zg1, bg1r)));
            BAR_A();          // g1 published -> phase 2 (dx + h) starts
            __syncthreads();  // B
        }
    } else if (tid >= 160) {
        // ===================== dx-warps (phase-2 critical chain) ==================
        const int q = tid - 160;        // 0..63
        const int j = q;

        float wg2r[128];
        #pragma unroll
        for (int i = 0; i < 128; i++) wg2r[i] = Wg2[i * NXX + j];
        const float bg2r = bg2[j];

        const size_t u_base0 = (size_t)(b0 + 0) * TT * NUU + q;  // q<32 duty
        const size_t u_base1 = (size_t)(b0 + 1) * TT * NUU + q;

        float xr0 = x0[(size_t)(b0 + 0) * NXX + j];
        float xr1 = x0[(size_t)(b0 + 1) * NXX + j];
        float* oxp0 = out_x + (size_t)(b0 + 0) * TT * NXX + j;
        float* oxp1 = out_x + (size_t)(b0 + 1) * TT * NXX + j;

        __syncthreads();  // init visible

        const ulonglong2* g2 = (const ulonglong2*)&g1s2[0];

        #pragma unroll 1
        for (int t = 0; t < TT; t++) {
            const int pn = (t + 1) & 1;

            // ---- phase 1: launch u(t+1) loads first, then record x_t ----
            float un0 = 0.f, un1 = 0.f;
            if (q < 32) {
                int tn = (t + 1 < TT) ? (t + 1) : (TT - 1);
                un0 = u[u_base0 + (size_t)tn * NUU];
                un1 = u[u_base1 + (size_t)tn * NUU];
            }
            *oxp0 = xr0;  oxp0 += NXX;
            *oxp1 = xr1;  oxp1 += NXX;
            BAR_A();  // g1 ready

            // ---- phase 2: packed sequential 128-dot (ascending i) ----
            u64 dxa = pk2(0.f, 0.f);
            #pragma unroll
            for (int i2 = 0; i2 < 64; i2++) {
                const ulonglong2 v = g2[i2];
                dxa = fma2(v.x, pk2(wg2r[2*i2+0], wg2r[2*i2+0]), dxa);
                dxa = fma2(v.y, pk2(wg2r[2*i2+1], wg2r[2*i2+1]), dxa);
            }
            float dxa0, dxa1; upk2(dxa, dxa0, dxa1);
            // pinned HLO order: x_{t+1} = x + (dot + bg2)
            xr0 = __fadd_rn(xr0, __fadd_rn(dxa0, bg2r));
            xr1 = __fadd_rn(xr1, __fadd_rn(dxa1, bg2r));
            sxu2[pn][j] = make_float2(xr0, xr1);
            if (q < 32) sxu2[pn][64 + q] = make_float2(un0, un1);
            __syncthreads();  // B
        }
    } else if (tid >= 32) {
        // ===================== h-warps (phase-2 window: A -> B) ===================
        const int h = tid - 32;         // 0..127
        float wh1r[64];
        #pragma unroll
        for (int k = 0; k < 64; k++) wh1r[k] = Wh1[k * HH + h];
        const float bh1r = bh1[h];

        __syncthreads();  // init visible

        #pragma unroll 1
        for (int t = 0; t < TT; t++) {
            const int p = t & 1;
            BAR_A();  // enter phase 2 (keeps our LDS/FMA out of the gated phase 1)

            const ulonglong2* x2 = (const ulonglong2*)&sxu2[p][0];
            u64 zh = pk2(0.f, 0.f);
            #pragma unroll
            for (int k2 = 0; k2 < 32; k2++) {
                const ulonglong2 v = x2[k2];
                zh = fma2(v.x, pk2(wh1r[2*k2+0], wh1r[2*k2+0]), zh);
                zh = fma2(v.y, pk2(wh1r[2*k2+1], wh1r[2*k2+1]), zh);
            }
            float zh0, zh1; upk2(zh, zh0, zh1);
            h1p2[p][h] = make_float2(xla_tanh(__fadd_rn(zh0, bh1r)),
                                     xla_tanh(__fadd_rn(zh1, bh1r)));
            __syncthreads();  // B: h1 committed with state
        }
    } else {
        // ===================== y-warp (wid 0, lagged, off the gate) ===============
        const int oo = tid;             // 0..31; active if oo<16

        float wh2r[128];
        const int oc = (oo < 16) ? oo : 0;
        #pragma unroll
        for (int i = 0; i < 128; i++) wh2r[i] = Wh2[i * NYY + oc];
        const float bh2r = bh2[oc];

        float* oyp0 = out_y + (size_t)(b0 + 0) * TT * NYY + oc;
        float* oyp1 = out_y + (size_t)(b0 + 1) * TT * NYY + oc;

        __syncthreads();  // init visible

        #pragma unroll 1
        for (int t = 0; t < TT; t++) {
            __syncthreads();  // B(t): h1p[t&1] ready
            const int pp = t & 1;
            const ulonglong2* h2 = (const ulonglong2*)&h1p2[pp][0];
            u64 ya = pk2(0.f, 0.f);
            #pragma unroll
            for (int i2 = 0; i2 < 64; i2++) {
                const ulonglong2 v = h2[i2];
                ya = fma2(v.x, pk2(wh2r[2*i2+0], wh2r[2*i2+0]), ya);
                ya = fma2(v.y, pk2(wh2r[2*i2+1], wh2r[2*i2+1]), ya);
            }
            float ya0, ya1; upk2(ya, ya0, ya1);
            if (oo < 16) {
                *oyp0 = __fadd_rn(ya0, bh2r);  oyp0 += NYY;
                *oyp1 = __fadd_rn(ya1, bh2r);  oyp1 += NYY;
            }
        }
    }
}

extern "C" void kernel_launch(void* const* d_in, const int* in_sizes, int n_in,
                              void* d_out, int out_size)
{
    const float* x0  = (const float*)d_in[0];
    const float* u   = (const float*)d_in[1];
    const float* Wg1 = (const float*)d_in[2];
    const float* bg1 = (const float*)d_in[3];
    const float* Wg2 = (const float*)d_in[4];
    const float* bg2 = (const float*)d_in[5];
    const float* Wh1 = (const float*)d_in[6];
    const float* bh1 = (const float*)d_in[7];
    const float* Wh2 = (const float*)d_in[8];
    const float* bh2 = (const float*)d_in[9];

    float* out_x = (float*)d_out;
    float* out_y = out_x + (size_t)BB * TT * NXX;

    ssm_kernel<<<BB / 2, 352>>>(x0, u, Wg1, bg1, Wg2, bg2,
                                Wh1, bh1, Wh2, bh2, out_x, out_y);
}

// round 13
// speedup vs baseline: 1.0377x; 1.0001x over previous
#include <cuda_runtime.h>
#include <cstddef>

#define BB 256
#define TT 2048
#define NXX 64
#define NUU 32
#define NYY 16
#define HH 128

typedef unsigned long long u64;

// BAR_A: h-warps + dx-warps + g-warps (320 threads, tid 32..351). B: full CTA (352).
#define BAR_A() asm volatile("bar.sync 1, 320;" ::: "memory")

// Packed fp32x2 helpers (per-lane IEEE fma.rn, identical to scalar fma.rn.f32).
__device__ __forceinline__ u64 pk2(float lo, float hi) {
    u64 r; asm("mov.b64 %0, {%1, %2};" : "=l"(r) : "f"(lo), "f"(hi)); return r;
}
__device__ __forceinline__ void upk2(u64 v, float& lo, float& hi) {
    asm("mov.b64 {%0, %1}, %2;" : "=f"(lo), "=f"(hi) : "l"(v));
}
__device__ __forceinline__ u64 fma2(u64 a, u64 b, u64 c) {
    u64 d; asm("fma.rn.f32x2 %0, %1, %2, %3;" : "=l"(d) : "l"(a), "l"(b), "l"(c)); return d;
}

// IEEE round-to-nearest divide, immune to fast-math substitution.
__device__ __forceinline__ float fdiv_rn(float a, float b) {
    float r; asm("div.rn.f32 %0, %1, %2;" : "=f"(r) : "f"(a), "f"(b)); return r;
}

// Exact replication of XLA EmitFastTanh (FMA-capable target). DO NOT TOUCH.
__device__ __forceinline__ float xla_tanh(float x) {
    const float kClamp = 7.99881172180175781f;
    float xc = fmaxf(-kClamp, fminf(x, kClamp));
    float x2 = __fmul_rn(xc, xc);
    float p = fmaf(x2, -2.76076847742355e-16f, 2.00018790482477e-13f);
    p = fmaf(x2, p, -8.60467152213735e-11f);
    p = fmaf(x2, p,  5.12229709037114e-08f);
    p = fmaf(x2, p,  1.48572235717979e-05f);
    p = fmaf(x2, p,  6.37261928875436e-04f);
    p = fmaf(x2, p,  4.89352455891786e-03f);
    float num = __fmul_rn(xc, p);
    float q = fmaf(x2, 1.19825839466702e-06f, 1.18534705686654e-04f);
    q = fmaf(x2, q, 2.26843463243900e-03f);
    q = fmaf(x2, q, 4.89352518554385e-03f);
    float r = fdiv_rn(num, q);
    return (fabsf(x) < 0.0004f) ? x : r;
}

// Packed dot with explicit software prefetch (rotating 4-vector buffer = 8-link
// lookahead = 32 cyc >= LDS latency). Accumulation: single chain, k ascending
// within each lane — bit-identical to the straight loop.
template <int NVEC>
__device__ __forceinline__ u64 dot_prefetch(const ulonglong2* __restrict__ src,
                                            const float* __restrict__ w) {
    ulonglong2 buf[4];
    #pragma unroll
    for (int i = 0; i < 4; i++) buf[i] = src[i];
    u64 acc = pk2(0.f, 0.f);
    #pragma unroll
    for (int k2 = 0; k2 < NVEC; k2++) {
        const ulonglong2 v = buf[k2 & 3];
        if (k2 + 4 < NVEC) buf[k2 & 3] = src[k2 + 4];
        acc = fma2(v.x, pk2(w[2*k2+0], w[2*k2+0]), acc);
        acc = fma2(v.y, pk2(w[2*k2+1], w[2*k2+1]), acc);
    }
    return acc;
}

// 128 CTAs x 352 threads; 2 batch elements per CTA, packed lane-wise (f32x2).
//   tid   0.. 31 : y-warp (joins B only; lagged).
//   tid  32..159 : h-warps (phase 2: A -> B).
//   tid 160..223 : dx-warps (phase-2 critical chain).
//   tid 224..351 : g-warps (phase-1 critical chain).
// Per-lane accumulation orders identical to R6-R12 passing kernels (bit-exact).

__global__ __launch_bounds__(352, 1)
void ssm_kernel(const float* __restrict__ x0,
                const float* __restrict__ u,
                const float* __restrict__ Wg1, const float* __restrict__ bg1,
                const float* __restrict__ Wg2, const float* __restrict__ bg2,
                const float* __restrict__ Wh1, const float* __restrict__ bh1,
                const float* __restrict__ Wh2, const float* __restrict__ bh2,
                float* __restrict__ out_x, float* __restrict__ out_y)
{
    __shared__ __align__(16) float2 sxu2[2][96];   // [parity][k] = (e0,e1); 0..63 x, 64..95 u
    __shared__ __align__(16) float2 g1s2[HH];      // tanh(g layer-1) pairs
    __shared__ __align__(16) float2 h1p2[2][HH];   // tanh(h layer-1) pairs, double buffer

    const int tid = threadIdx.x;
    const int b0  = blockIdx.x * 2;

    // ---- init: x0, u0 into parity-0 buffer as pairs ----
    if (tid < 64) {
        sxu2[0][tid] = make_float2(x0[(size_t)(b0 + 0) * NXX + tid],
                                   x0[(size_t)(b0 + 1) * NXX + tid]);
    } else if (tid < 96) {
        int k = tid - 64;
        sxu2[0][64 + k] = make_float2(u[(size_t)(b0 + 0) * TT * NUU + k],
                                      u[(size_t)(b0 + 1) * TT * NUU + k]);
    }

    if (tid >= 224) {
        // ===================== g-warps (phase-1 critical) =====================
        const int h = tid - 224;
        float wg1r[96];
        #pragma unroll
        for (int k = 0; k < 96; k++) wg1r[k] = Wg1[k * HH + h];
        const float bg1r = bg1[h];

        __syncthreads();  // init visible

        #pragma unroll 1
        for (int t = 0; t < TT; t++) {
            const int p = t & 1;
            const ulonglong2* x2 = (const ulonglong2*)&sxu2[p][0];

            u64 zg = dot_prefetch<48>(x2, wg1r);
            float zg0, zg1; upk2(zg, zg0, zg1);
            g1s2[h] = make_float2(xla_tanh(__fadd_rn(zg0, bg1r)),
                                  xla_tanh(__fadd_rn(zg1, bg1r)));
            BAR_A();          // g1 published -> phase 2 (dx + h) starts
            __syncthreads();  // B
        }
    } else if (tid >= 160) {
        // ===================== dx-warps (phase-2 critical chain) ==================
        const int q = tid - 160;        // 0..63
        const int j = q;

        float wg2r[128];
        #pragma unroll
        for (int i = 0; i < 128; i++) wg2r[i] = Wg2[i * NXX + j];
        const float bg2r = bg2[j];

        const size_t u_base0 = (size_t)(b0 + 0) * TT * NUU + q;  // q<32 duty
        const size_t u_base1 = (size_t)(b0 + 1) * TT * NUU + q;

        float xr0 = x0[(size_t)(b0 + 0) * NXX + j];
        float xr1 = x0[(size_t)(b0 + 1) * NXX + j];
        float* oxp0 = out_x + (size_t)(b0 + 0) * TT * NXX + j;
        float* oxp1 = out_x + (size_t)(b0 + 1) * TT * NXX + j;

        __syncthreads();  // init visible

        const ulonglong2* g2 = (const ulonglong2*)&g1s2[0];

        #pragma unroll 1
        for (int t = 0; t < TT; t++) {
            const int pn = (t + 1) & 1;

            // ---- phase 1: launch u(t+1) loads first, then record x_t ----
            float un0 = 0.f, un1 = 0.f;
            if (q < 32) {
                int tn = (t + 1 < TT) ? (t + 1) : (TT - 1);
                un0 = u[u_base0 + (size_t)tn * NUU];
                un1 = u[u_base1 + (size_t)tn * NUU];
            }
            *oxp0 = xr0;  oxp0 += NXX;
            *oxp1 = xr1;  oxp1 += NXX;
            BAR_A();  // g1 ready

            // ---- phase 2: packed sequential 128-dot (ascending i) ----
            u64 dxa = dot_prefetch<64>(g2, wg2r);
            float dxa0, dxa1; upk2(dxa, dxa0, dxa1);
            // pinned HLO order: x_{t+1} = x + (dot + bg2)
            xr0 = __fadd_rn(xr0, __fadd_rn(dxa0, bg2r));
            xr1 = __fadd_rn(xr1, __fadd_rn(dxa1, bg2r));
            sxu2[pn][j] = make_float2(xr0, xr1);
            if (q < 32) sxu2[pn][64 + q] = make_float2(un0, un1);
            __syncthreads();  // B
        }
    } else if (tid >= 32) {
        // ===================== h-warps (phase-2 window: A -> B) ===================
        const int h = tid - 32;         // 0..127
        float wh1r[64];
        #pragma unroll
        for (int k = 0; k < 64; k++) wh1r[k] = Wh1[k * HH + h];
        const float bh1r = bh1[h];

        __syncthreads();  // init visible

        #pragma unroll 1
        for (int t = 0; t < TT; t++) {
            const int p = t & 1;
            BAR_A();  // enter phase 2

            const ulonglong2* x2 = (const ulonglong2*)&sxu2[p][0];
            u64 zh = dot_prefetch<32>(x2, wh1r);
            float zh0, zh1; upk2(zh, zh0, zh1);
            h1p2[p][h] = make_float2(xla_tanh(__fadd_rn(zh0, bh1r)),
                                     xla_tanh(__fadd_rn(zh1, bh1r)));
            __syncthreads();  // B: h1 committed with state
        }
    } else {
        // ===================== y-warp (wid 0, lagged, off the gate) ===============
        const int oo = tid;             // 0..31; active if oo<16

        float wh2r[128];
        const int oc = (oo < 16) ? oo : 0;
        #pragma unroll
        for (int i = 0; i < 128; i++) wh2r[i] = Wh2[i * NYY + oc];
        const float bh2r = bh2[oc];

        float* oyp0 = out_y + (size_t)(b0 + 0) * TT * NYY + oc;
        float* oyp1 = out_y + (size_t)(b0 + 1) * TT * NYY + oc;

        __syncthreads();  // init visible

        #pragma unroll 1
        for (int t = 0; t < TT; t++) {
            __syncthreads();  // B(t): h1p[t&1] ready
            const int pp = t & 1;
            const ulonglong2* h2 = (const ulonglong2*)&h1p2[pp][0];
            u64 ya = dot_prefetch<64>(h2, wh2r);
            float ya0, ya1; upk2(ya, ya0, ya1);
            if (oo < 16) {
                *oyp0 = __fadd_rn(ya0, bh2r);  oyp0 += NYY;
                *oyp1 = __fadd_rn(ya1, bh2r);  oyp1 += NYY;
            }
        }
    }
}

extern "C" void kernel_launch(void* const* d_in, const int* in_sizes, int n_in,
                              void* d_out, int out_size)
{
    const float* x0  = (const float*)d_in[0];
    const float* u   = (const float*)d_in[1];
    const float* Wg1 = (const float*)d_in[2];
    const float* bg1 = (const float*)d_in[3];
    const float* Wg2 = (const float*)d_in[4];
    const float* bg2 = (const float*)d_in[5];
    const float* Wh1 = (const float*)d_in[6];
    const float* bh1 = (const float*)d_in[7];
    const float* Wh2 = (const float*)d_in[8];
    const float* bh2 = (const float*)d_in[9];

    float* out_x = (float*)d_out;
    float* out_y = out_x + (size_t)BB * TT * NXX;

    ssm_kernel<<<BB / 2, 352>>>(x0, u, Wg1, bg1, Wg2, bg2,
                                Wh1, bh1, Wh2, bh2, out_x, out_y);
}

// round 14
// speedup vs baseline: 1.1318x; 1.0907x over previous
#include <cuda_runtime.h>
#include <cstddef>

#define BB 256
#define TT 2048
#define NXX 64
#define NUU 32
#define NYY 16
#define HH 128

typedef unsigned long long u64;

// BAR_A: ALL 352 threads (y now waits for phase 2). B: full CTA __syncthreads.
#define BAR_A() asm volatile("bar.sync 1, 352;" ::: "memory")

// Packed fp32x2 helpers (per-lane IEEE fma.rn, identical to scalar fma.rn.f32).
__device__ __forceinline__ u64 pk2(float lo, float hi) {
    u64 r; asm("mov.b64 %0, {%1, %2};" : "=l"(r) : "f"(lo), "f"(hi)); return r;
}
__device__ __forceinline__ void upk2(u64 v, float& lo, float& hi) {
    asm("mov.b64 {%0, %1}, %2;" : "=f"(lo), "=f"(hi) : "l"(v));
}
__device__ __forceinline__ u64 fma2(u64 a, u64 b, u64 c) {
    u64 d; asm("fma.rn.f32x2 %0, %1, %2, %3;" : "=l"(d) : "l"(a), "l"(b), "l"(c)); return d;
}

// IEEE round-to-nearest divide, immune to fast-math substitution.
__device__ __forceinline__ float fdiv_rn(float a, float b) {
    float r; asm("div.rn.f32 %0, %1, %2;" : "=f"(r) : "f"(a), "f"(b)); return r;
}

// Exact replication of XLA EmitFastTanh (FMA-capable target). DO NOT TOUCH.
__device__ __forceinline__ float xla_tanh(float x) {
    const float kClamp = 7.99881172180175781f;
    float xc = fmaxf(-kClamp, fminf(x, kClamp));
    float x2 = __fmul_rn(xc, xc);
    float p = fmaf(x2, -2.76076847742355e-16f, 2.00018790482477e-13f);
    p = fmaf(x2, p, -8.60467152213735e-11f);
    p = fmaf(x2, p,  5.12229709037114e-08f);
    p = fmaf(x2, p,  1.48572235717979e-05f);
    p = fmaf(x2, p,  6.37261928875436e-04f);
    p = fmaf(x2, p,  4.89352455891786e-03f);
    float num = __fmul_rn(xc, p);
    float q = fmaf(x2, 1.19825839466702e-06f, 1.18534705686654e-04f);
    q = fmaf(x2, q, 2.26843463243900e-03f);
    q = fmaf(x2, q, 4.89352518554385e-03f);
    float r = fdiv_rn(num, q);
    return (fabsf(x) < 0.0004f) ? x : r;
}

// Packed dot: single per-lane chain, k ascending — bit-identical to scalar loop.
template <int NVEC>
__device__ __forceinline__ u64 dot_packed(const ulonglong2* __restrict__ src,
                                          const float* __restrict__ w) {
    u64 acc = pk2(0.f, 0.f);
    #pragma unroll
    for (int k2 = 0; k2 < NVEC; k2++) {
        const ulonglong2 v = src[k2];
        acc = fma2(v.x, pk2(w[2*k2+0], w[2*k2+0]), acc);
        acc = fma2(v.y, pk2(w[2*k2+1], w[2*k2+1]), acc);
    }
    return acc;
}

// 128 CTAs x 352 threads; 2 batch elements per CTA, packed lane-wise (f32x2).
//   tid   0.. 31 : y-warp — scalar dot, runs in PHASE 2 (joins BAR_A), lagged 1 step.
//   tid  32..159 : h-warps (phase 2: A -> B).
//   tid 160..223 : dx-warps (phase-2 critical chain).
//   tid 224..351 : g-warps (phase-1 critical chain; phase 1 now g-only per SMSP).
// Per-lane/per-output accumulation orders identical to R6-R13 kernels (bit-exact).

__global__ __launch_bounds__(352, 1)
void ssm_kernel(const float* __restrict__ x0,
                const float* __restrict__ u,
                const float* __restrict__ Wg1, const float* __restrict__ bg1,
                const float* __restrict__ Wg2, const float* __restrict__ bg2,
                const float* __restrict__ Wh1, const float* __restrict__ bh1,
                const float* __restrict__ Wh2, const float* __restrict__ bh2,
                float* __restrict__ out_x, float* __restrict__ out_y)
{
    __shared__ __align__(16) float2 sxu2[2][96];   // [parity][k] = (e0,e1); 0..63 x, 64..95 u
    __shared__ __align__(16) float2 g1s2[HH];      // tanh(g layer-1) pairs
    __shared__ __align__(16) float2 h1p2[2][HH];   // tanh(h layer-1) pairs, double buffer

    const int tid = threadIdx.x;
    const int b0  = blockIdx.x * 2;

    // ---- init: x0, u0 into parity-0 buffer as pairs ----
    if (tid < 64) {
        sxu2[0][tid] = make_float2(x0[(size_t)(b0 + 0) * NXX + tid],
                                   x0[(size_t)(b0 + 1) * NXX + tid]);
    } else if (tid < 96) {
        int k = tid - 64;
        sxu2[0][64 + k] = make_float2(u[(size_t)(b0 + 0) * TT * NUU + k],
                                      u[(size_t)(b0 + 1) * TT * NUU + k]);
    }

    if (tid >= 224) {
        // ===================== g-warps (phase-1 critical) =====================
        const int h = tid - 224;
        float wg1r[96];
        #pragma unroll
        for (int k = 0; k < 96; k++) wg1r[k] = Wg1[k * HH + h];
        const float bg1r = bg1[h];

        __syncthreads();  // init visible

        #pragma unroll 1
        for (int t = 0; t < TT; t++) {
            const int p = t & 1;
            const ulonglong2* x2 = (const ulonglong2*)&sxu2[p][0];

            u64 zg = dot_packed<48>(x2, wg1r);
            float zg0, zg1; upk2(zg, zg0, zg1);
            g1s2[h] = make_float2(xla_tanh(__fadd_rn(zg0, bg1r)),
                                  xla_tanh(__fadd_rn(zg1, bg1r)));
            BAR_A();          // g1 published -> phase 2 (dx + h + y) starts
            __syncthreads();  // B
        }
    } else if (tid >= 160) {
        // ===================== dx-warps (phase-2 critical chain) ==================
        const int q = tid - 160;        // 0..63
        const int j = q;

        float wg2r[128];
        #pragma unroll
        for (int i = 0; i < 128; i++) wg2r[i] = Wg2[i * NXX + j];
        const float bg2r = bg2[j];

        const size_t u_base0 = (size_t)(b0 + 0) * TT * NUU + q;  // q<32 duty
        const size_t u_base1 = (size_t)(b0 + 1) * TT * NUU + q;

        float xr0 = x0[(size_t)(b0 + 0) * NXX + j];
        float xr1 = x0[(size_t)(b0 + 1) * NXX + j];
        float* oxp0 = out_x + (size_t)(b0 + 0) * TT * NXX + j;
        float* oxp1 = out_x + (size_t)(b0 + 1) * TT * NXX + j;

        __syncthreads();  // init visible

        const ulonglong2* g2 = (const ulonglong2*)&g1s2[0];

        #pragma unroll 1
        for (int t = 0; t < TT; t++) {
            const int pn = (t + 1) & 1;

            // ---- phase 1: launch u(t+1) loads first, then record x_t ----
            float un0 = 0.f, un1 = 0.f;
            if (q < 32) {
                int tn = (t + 1 < TT) ? (t + 1) : (TT - 1);
                un0 = u[u_base0 + (size_t)tn * NUU];
                un1 = u[u_base1 + (size_t)tn * NUU];
            }
            *oxp0 = xr0;  oxp0 += NXX;
            *oxp1 = xr1;  oxp1 += NXX;
            BAR_A();  // g1 ready

            // ---- phase 2: packed sequential 128-dot (ascending i) ----
            u64 dxa = dot_packed<64>(g2, wg2r);
            float dxa0, dxa1; upk2(dxa, dxa0, dxa1);
            // pinned HLO order: x_{t+1} = x + (dot + bg2)
            xr0 = __fadd_rn(xr0, __fadd_rn(dxa0, bg2r));
            xr1 = __fadd_rn(xr1, __fadd_rn(dxa1, bg2r));
            sxu2[pn][j] = make_float2(xr0, xr1);
            if (q < 32) sxu2[pn][64 + q] = make_float2(un0, un1);
            __syncthreads();  // B
        }
    } else if (tid >= 32) {
        // ===================== h-warps (phase-2 window: A -> B) ===================
        const int h = tid - 32;         // 0..127
        float wh1r[64];
        #pragma unroll
        for (int k = 0; k < 64; k++) wh1r[k] = Wh1[k * HH + h];
        const float bh1r = bh1[h];

        __syncthreads();  // init visible

        #pragma unroll 1
        for (int t = 0; t < TT; t++) {
            const int p = t & 1;
            BAR_A();  // enter phase 2

            const ulonglong2* x2 = (const ulonglong2*)&sxu2[p][0];
            u64 zh = dot_packed<32>(x2, wh1r);
            float zh0, zh1; upk2(zh, zh0, zh1);
            h1p2[p][h] = make_float2(xla_tanh(__fadd_rn(zh0, bh1r)),
                                     xla_tanh(__fadd_rn(zh1, bh1r)));
            __syncthreads();  // B: h1 committed with state
        }
    } else {
        // ====== y-warp: scalar dot, phase-2 window, lagged one step ==============
        const int oo = tid;             // 0..31
        const int e  = oo >> 4;         // element
        const int oc = oo & 15;         // output col

        float wh2r[128];
        #pragma unroll
        for (int i = 0; i < 128; i++) wh2r[i] = Wh2[i * NYY + oc];
        const float bh2r = bh2[oc];

        float* oyp = out_y + (size_t)(b0 + e) * TT * NYY + oc;

        __syncthreads();  // init visible

        #pragma unroll 1
        for (int t = 0; t < TT; t++) {
            BAR_A();  // enter phase 2; h1p[(t-1)&1] is stable (h writes [t&1])
            if (t > 0) {
                const int pp = (t - 1) & 1;
                const float4* h4 = (const float4*)&h1p2[pp][0];
                float ya = 0.0f;
                #pragma unroll
                for (int i2 = 0; i2 < 64; i2++) {
                    const float4 v = h4[i2];           // pairs (2*i2, 2*i2+1)
                    float a0 = (e == 0) ? v.x : v.y;   // h1[e][2*i2]
                    float a1 = (e == 0) ? v.z : v.w;   // h1[e][2*i2+1]
                    ya = fmaf(a0, wh2r[2*i2+0], ya);
                    ya = fmaf(a1, wh2r[2*i2+1], ya);
                }
                oyp[(size_t)(t - 1) * NYY] = __fadd_rn(ya, bh2r);
            }
            __syncthreads();  // B
        }
        // drain: y(TT-1) from h1p[(TT-1)&1] (no further writers)
        {
            const int pp = (TT - 1) & 1;
            const float4* h4 = (const float4*)&h1p2[pp][0];
            float ya = 0.0f;
            #pragma unroll
            for (int i2 = 0; i2 < 64; i2++) {
                const float4 v = h4[i2];
                float a0 = (e == 0) ? v.x : v.y;
                float a1 = (e == 0) ? v.z : v.w;
                ya = fmaf(a0, wh2r[2*i2+0], ya);
                ya = fmaf(a1, wh2r[2*i2+1], ya);
            }
            oyp[(size_t)(TT - 1) * NYY] = __fadd_rn(ya, bh2r);
        }
    }
}

extern "C" void kernel_launch(void* const* d_in, const int* in_sizes, int n_in,
                              void* d_out, int out_size)
{
    const float* x0  = (const float*)d_in[0];
    const float* u   = (const float*)d_in[1];
    const float* Wg1 = (const float*)d_in[2];
    const float* bg1 = (const float*)d_in[3];
    const float* Wg2 = (const float*)d_in[4];
    const float* bg2 = (const float*)d_in[5];
    const float* Wh1 = (const float*)d_in[6];
    const float* bh1 = (const float*)d_in[7];
    const float* Wh2 = (const float*)d_in[8];
    const float* bh2 = (const float*)d_in[9];

    float* out_x = (float*)d_out;
    float* out_y = out_x + (size_t)BB * TT * NXX;

    ssm_kernel<<<BB / 2, 352>>>(x0, u, Wg1, bg1, Wg2, bg2,
                                Wh1, bh1, Wh2, bh2, out_x, out_y);
}